// round 1
// baseline (speedup 1.0000x reference)
#include <cuda_runtime.h>
#include <cuda_bf16.h>

#define BB      16384
#define NSITES  784
#define DD      8
#define OO      10
#define LABEL   392
#define LLEFT   391   // sites 1..391
#define LRIGHT  390   // sites 393..782

// ---------------- scratch (static device globals; no runtime alloc) ----------------
__device__ float g_pT[NSITES * BB];                       // transposed p: [site][b]
__device__ __align__(16) float  g_WL[LLEFT * 128];        // per site: [w0 d*8+e (64)] [diff (64)]
__device__ __align__(16) float  g_WR[LRIGHT * 128];
__device__ __align__(16) float2 g_WLab[DD * DD * OO];     // [d][e][o] -> (w0, diff)
__device__ float g_w0c[16];                               // [0..7]=w0[f=0], [8..15]=diff
__device__ float g_wlastc[16];                            // [0..7]=f0, [8..15]=diff
__device__ __align__(16) float g_vleft[BB * 8];
__device__ __align__(16) float g_u[BB * 8];

// ---------------- kernel 1: tiled transpose x[B,N] -> g_pT[N,B] ----------------
__global__ void transpose_kernel(const float* __restrict__ x) {
    __shared__ float tile[32][33];
    int n0 = blockIdx.x * 32;
    int b0 = blockIdx.y * 32;
    #pragma unroll
    for (int r = 0; r < 32; r += 8) {
        int n = n0 + threadIdx.x;
        int b = b0 + threadIdx.y + r;
        if (n < NSITES) tile[threadIdx.y + r][threadIdx.x] = x[b * NSITES + n];
    }
    __syncthreads();
    #pragma unroll
    for (int r = 0; r < 32; r += 8) {
        int n = n0 + threadIdx.y + r;
        int b = b0 + threadIdx.x;
        if (n < NSITES) g_pT[n * BB + b] = tile[threadIdx.x][threadIdx.y + r];
    }
}

// ---------------- kernel 2: weight prep (w0 / diff packing) ----------------
__global__ void prep_weights(const float* __restrict__ wl,
                             const float* __restrict__ wlab,
                             const float* __restrict__ wr,
                             const float* __restrict__ w0,
                             const float* __restrict__ wlast) {
    int idx = blockIdx.x * blockDim.x + threadIdx.x;
    if (idx < LLEFT * 64) {
        int i = idx >> 6; int de = idx & 63; int d = de >> 3; int e = de & 7;
        float a = wl[((i * 8 + d) * 2 + 0) * 8 + e];
        float b = wl[((i * 8 + d) * 2 + 1) * 8 + e];
        g_WL[i * 128 + d * 8 + e] = a;
        g_WL[i * 128 + 64 + d * 8 + e] = b - a;
        return;
    }
    idx -= LLEFT * 64;
    if (idx < LRIGHT * 64) {
        int i = idx >> 6; int de = idx & 63; int d = de >> 3; int e = de & 7;
        float a = wr[((i * 8 + d) * 2 + 0) * 8 + e];
        float b = wr[((i * 8 + d) * 2 + 1) * 8 + e];
        g_WR[i * 128 + d * 8 + e] = a;
        g_WR[i * 128 + 64 + d * 8 + e] = b - a;
        return;
    }
    idx -= LRIGHT * 64;
    if (idx < DD * DD * OO) {
        int o = idx % OO; int de = idx / OO; int e = de % DD; int d = de / DD;
        float a = wlab[((d * 2 + 0) * 8 + e) * OO + o];
        float b = wlab[((d * 2 + 1) * 8 + e) * OO + o];
        g_WLab[(d * 8 + e) * OO + o] = make_float2(a, b - a);
        return;
    }
    idx -= DD * DD * OO;
    if (idx < 8) {                    // w0 boundary: w0 shape [2,D] -> [f*8+d]
        g_w0c[idx]     = w0[idx];
        g_w0c[8 + idx] = w0[8 + idx] - w0[idx];
        return;
    }
    idx -= 8;
    if (idx < 8) {                    // w_last shape [D,2] -> [d*2+f]
        g_wlastc[idx]     = wlast[idx * 2 + 0];
        g_wlastc[8 + idx] = wlast[idx * 2 + 1] - wlast[idx * 2 + 0];
    }
}

// ---------------- kernel 3: both chains (left fwd / right backward), 1 thread = 1 batch row ----------------
__global__ __launch_bounds__(224, 1) void chain_kernel() {
    extern __shared__ float sw[];
    const int blk = blockIdx.x;
    const bool isLeft = (blk < 74);

    // stage this side's full per-site weight table into SMEM (uniform broadcast reads later)
    {
        const float4* g4 = (const float4*)(isLeft ? g_WL : g_WR);
        float4* s4 = (float4*)sw;
        const int n4 = (isLeft ? LLEFT * 128 : LRIGHT * 128) / 4;
        for (int i = threadIdx.x; i < n4; i += 224) s4[i] = g4[i];
    }
    __syncthreads();

    const int b = (isLeft ? blk : blk - 74) * 224 + threadIdx.x;
    if (b >= BB) return;

    if (isLeft) {
        float v[8];
        float p0 = g_pT[b];                       // site 0
        #pragma unroll
        for (int d = 0; d < 8; d++) v[d] = fmaf(p0, g_w0c[8 + d], g_w0c[d]);

        float pA = g_pT[1 * BB + b];
        float pB = g_pT[2 * BB + b];
        for (int s = 0; s < LLEFT; s++) {
            const float pc = pA;
            pA = pB;
            pB = g_pT[(s + 3) * BB + b];          // prefetch (site s+3 <= 393, always valid)
            const float4* w4 = (const float4*)(sw + s * 128);
            float vn[8];
            #pragma unroll
            for (int e = 0; e < 8; e++) vn[e] = 0.0f;
            #pragma unroll
            for (int d = 0; d < 8; d++) {
                const float4 a0 = w4[d * 2 + 0];
                const float4 a1 = w4[d * 2 + 1];
                const float4 c0 = w4[16 + d * 2 + 0];
                const float4 c1 = w4[16 + d * 2 + 1];
                const float vd = v[d];
                const float vp = vd * pc;
                vn[0] = fmaf(vd, a0.x, fmaf(vp, c0.x, vn[0]));
                vn[1] = fmaf(vd, a0.y, fmaf(vp, c0.y, vn[1]));
                vn[2] = fmaf(vd, a0.z, fmaf(vp, c0.z, vn[2]));
                vn[3] = fmaf(vd, a0.w, fmaf(vp, c0.w, vn[3]));
                vn[4] = fmaf(vd, a1.x, fmaf(vp, c1.x, vn[4]));
                vn[5] = fmaf(vd, a1.y, fmaf(vp, c1.y, vn[5]));
                vn[6] = fmaf(vd, a1.z, fmaf(vp, c1.z, vn[6]));
                vn[7] = fmaf(vd, a1.w, fmaf(vp, c1.w, vn[7]));
            }
            #pragma unroll
            for (int e = 0; e < 8; e++) v[e] = vn[e];
        }
        float4* dst = (float4*)(g_vleft + b * 8);
        dst[0] = make_float4(v[0], v[1], v[2], v[3]);
        dst[1] = make_float4(v[4], v[5], v[6], v[7]);
    } else {
        // backward vector chain: u = M_393 * (... * (M_782 * r))
        float u[8];
        float pl = g_pT[(NSITES - 1) * BB + b];   // site 783
        #pragma unroll
        for (int d = 0; d < 8; d++) u[d] = fmaf(pl, g_wlastc[8 + d], g_wlastc[d]);

        float pA = g_pT[782 * BB + b];            // site for s = 389
        float pB = g_pT[781 * BB + b];
        for (int s = LRIGHT - 1; s >= 0; s--) {
            const float pc = pA;
            pA = pB;
            pB = g_pT[(s + 391) * BB + b];        // prefetch (index >= 391, always valid)
            const float4* w4 = (const float4*)(sw + s * 128);
            float un[8];
            #pragma unroll
            for (int d = 0; d < 8; d++) {
                const float4 a0 = w4[d * 2 + 0];
                const float4 a1 = w4[d * 2 + 1];
                const float4 c0 = w4[16 + d * 2 + 0];
                const float4 c1 = w4[16 + d * 2 + 1];
                float acc0 = a0.x * u[0];
                acc0 = fmaf(a0.y, u[1], acc0);
                acc0 = fmaf(a0.z, u[2], acc0);
                acc0 = fmaf(a0.w, u[3], acc0);
                acc0 = fmaf(a1.x, u[4], acc0);
                acc0 = fmaf(a1.y, u[5], acc0);
                acc0 = fmaf(a1.z, u[6], acc0);
                acc0 = fmaf(a1.w, u[7], acc0);
                float acc1 = c0.x * u[0];
                acc1 = fmaf(c0.y, u[1], acc1);
                acc1 = fmaf(c0.z, u[2], acc1);
                acc1 = fmaf(c0.w, u[3], acc1);
                acc1 = fmaf(c1.x, u[4], acc1);
                acc1 = fmaf(c1.y, u[5], acc1);
                acc1 = fmaf(c1.z, u[6], acc1);
                acc1 = fmaf(c1.w, u[7], acc1);
                un[d] = fmaf(pc, acc1, acc0);
            }
            #pragma unroll
            for (int d = 0; d < 8; d++) u[d] = un[d];
        }
        float4* dst = (float4*)(g_u + b * 8);
        dst[0] = make_float4(u[0], u[1], u[2], u[3]);
        dst[1] = make_float4(u[4], u[5], u[6], u[7]);
    }
}

// ---------------- kernel 4: label-site combine -> out[B,O] ----------------
__global__ __launch_bounds__(128) void label_kernel(float* __restrict__ out) {
    __shared__ float2 swl[DD * DD * OO];
    for (int i = threadIdx.x; i < DD * DD * OO; i += 128) swl[i] = g_WLab[i];
    __syncthreads();

    const int b = blockIdx.x * 128 + threadIdx.x;
    if (b >= BB) return;

    const float p = g_pT[LABEL * BB + b];
    float vl[8], uu[8];
    {
        const float4* s0 = (const float4*)(g_vleft + b * 8);
        float4 t0 = s0[0], t1 = s0[1];
        vl[0]=t0.x; vl[1]=t0.y; vl[2]=t0.z; vl[3]=t0.w;
        vl[4]=t1.x; vl[5]=t1.y; vl[6]=t1.z; vl[7]=t1.w;
        const float4* s1 = (const float4*)(g_u + b * 8);
        float4 r0 = s1[0], r1 = s1[1];
        uu[0]=r0.x; uu[1]=r0.y; uu[2]=r0.z; uu[3]=r0.w;
        uu[4]=r1.x; uu[5]=r1.y; uu[6]=r1.z; uu[7]=r1.w;
    }

    float acc[OO];
    #pragma unroll
    for (int o = 0; o < OO; o++) acc[o] = 0.0f;

    #pragma unroll
    for (int d = 0; d < 8; d++) {
        #pragma unroll
        for (int e = 0; e < 8; e++) {
            const float g  = vl[d] * uu[e];
            const float gp = g * p;
            const float2* wp = swl + (d * 8 + e) * OO;
            #pragma unroll
            for (int o = 0; o < OO; o++) {
                float2 wv = wp[o];
                acc[o] = fmaf(g, wv.x, fmaf(gp, wv.y, acc[o]));
            }
        }
    }
    #pragma unroll
    for (int o = 0; o < OO; o++) out[b * OO + o] = acc[o];
}

// ---------------- launcher ----------------
extern "C" void kernel_launch(void* const* d_in, const int* in_sizes, int n_in,
                              void* d_out, int out_size) {
    const float* x      = (const float*)d_in[0];
    const float* w0     = (const float*)d_in[1];
    const float* Wleft  = (const float*)d_in[2];
    const float* wlabel = (const float*)d_in[3];
    const float* Wright = (const float*)d_in[4];
    const float* wlast  = (const float*)d_in[5];
    float* out = (float*)d_out;

    const int chainSmem = LLEFT * 128 * (int)sizeof(float);   // 200192 B (covers both sides)
    cudaFuncSetAttribute(chain_kernel, cudaFuncAttributeMaxDynamicSharedMemorySize, chainSmem);

    transpose_kernel<<<dim3((NSITES + 31) / 32, BB / 32), dim3(32, 8)>>>(x);
    prep_weights<<<(LLEFT * 64 + LRIGHT * 64 + DD * DD * OO + 16 + 255) / 256, 256>>>(
        Wleft, wlabel, Wright, w0, wlast);
    chain_kernel<<<148, 224, chainSmem>>>();
    label_kernel<<<BB / 128, 128>>>(out);
}

// round 2
// speedup vs baseline: 1.4968x; 1.4968x over previous
#include <cuda_runtime.h>
#include <cuda_bf16.h>

#define BB      16384
#define NSITES  784
#define DD      8
#define OO      10
#define LABEL   392
#define LLEFT   391   // sites 1..391
#define LRIGHT  390   // sites 393..782 (stored reversed+transposed)

typedef unsigned long long u64;

// ---------------- packed f32x2 helpers (sm_103a FFMA2 path) ----------------
__device__ __forceinline__ u64 pk2(float a, float b) {
    u64 r; asm("mov.b64 %0, {%1, %2};" : "=l"(r) : "f"(a), "f"(b)); return r;
}
__device__ __forceinline__ void upk2(float& a, float& b, u64 r) {
    asm("mov.b64 {%0, %1}, %2;" : "=f"(a), "=f"(b) : "l"(r));
}
__device__ __forceinline__ u64 fma2(u64 a, u64 b, u64 c) {
    u64 d; asm("fma.rn.f32x2 %0, %1, %2, %3;" : "=l"(d) : "l"(a), "l"(b), "l"(c)); return d;
}
__device__ __forceinline__ u64 mul2(u64 a, u64 b) {
    u64 d; asm("mul.rn.f32x2 %0, %1, %2;" : "=l"(d) : "l"(a), "l"(b)); return d;
}
__device__ __forceinline__ u64 add2(u64 a, u64 b) {
    u64 d; asm("add.rn.f32x2 %0, %1, %2;" : "=l"(d) : "l"(a), "l"(b)); return d;
}

// ---------------- scratch ----------------
__device__ float g_pT[NSITES * BB];                   // [site][b]
__device__ __align__(16) float g_WL[LLEFT * 128];     // per step: A[i*8+j] (64) | C (64)
__device__ __align__(16) float g_WR[LRIGHT * 128];    // transposed + reversed
__device__ __align__(8)  float g_Alab[DD * DD * OO];  // [(d*8+e)*10+o]
__device__ __align__(8)  float g_Clab[DD * DD * OO];
__device__ float g_w0c[16];
__device__ float g_wlastc[16];
__device__ __align__(16) float g_vleft[BB * 8];
__device__ __align__(16) float g_u[BB * 8];

// ---------------- kernel 1: tiled transpose x[B,N] -> g_pT[N,B] ----------------
__global__ void transpose_kernel(const float* __restrict__ x) {
    __shared__ float tile[32][33];
    int n0 = blockIdx.x * 32;
    int b0 = blockIdx.y * 32;
    #pragma unroll
    for (int r = 0; r < 32; r += 8) {
        int n = n0 + threadIdx.x;
        int b = b0 + threadIdx.y + r;
        if (n < NSITES) tile[threadIdx.y + r][threadIdx.x] = x[b * NSITES + n];
    }
    __syncthreads();
    #pragma unroll
    for (int r = 0; r < 32; r += 8) {
        int n = n0 + threadIdx.y + r;
        int b = b0 + threadIdx.x;
        if (n < NSITES) g_pT[n * BB + b] = tile[threadIdx.x][threadIdx.y + r];
    }
}

// ---------------- kernel 2: weight prep ----------------
__global__ void prep_weights(const float* __restrict__ wl,
                             const float* __restrict__ wlab,
                             const float* __restrict__ wr,
                             const float* __restrict__ w0,
                             const float* __restrict__ wlast) {
    int idx = blockIdx.x * blockDim.x + threadIdx.x;
    if (idx < LLEFT * 64) {            // left: natural layout A[d][e]
        int s = idx >> 6; int r = idx & 63; int d = r >> 3; int e = r & 7;
        float a = wl[((s * 8 + d) * 2 + 0) * 8 + e];
        float b = wl[((s * 8 + d) * 2 + 1) * 8 + e];
        g_WL[s * 128 + d * 8 + e] = a;
        g_WL[s * 128 + 64 + d * 8 + e] = b - a;
        return;
    }
    idx -= LLEFT * 64;
    if (idx < LRIGHT * 64) {           // right: step t uses site (782 - t), transposed T[i=e][j=d] = M[d][e]
        int t = idx >> 6; int r = idx & 63; int i = r >> 3; int j = r & 7;
        int site_local = (LRIGHT - 1) - t;     // 0..389 within wr
        float a = wr[((site_local * 8 + j) * 2 + 0) * 8 + i];
        float b = wr[((site_local * 8 + j) * 2 + 1) * 8 + i];
        g_WR[t * 128 + i * 8 + j] = a;
        g_WR[t * 128 + 64 + i * 8 + j] = b - a;
        return;
    }
    idx -= LRIGHT * 64;
    if (idx < DD * DD * OO) {
        int o = idx % OO; int de = idx / OO; int e = de & 7; int d = de >> 3;
        float a = wlab[((d * 2 + 0) * 8 + e) * OO + o];
        float b = wlab[((d * 2 + 1) * 8 + e) * OO + o];
        g_Alab[(d * 8 + e) * OO + o] = a;
        g_Clab[(d * 8 + e) * OO + o] = b - a;
        return;
    }
    idx -= DD * DD * OO;
    if (idx < 8) {
        g_w0c[idx]     = w0[idx];
        g_w0c[8 + idx] = w0[8 + idx] - w0[idx];
        return;
    }
    idx -= 8;
    if (idx < 8) {
        g_wlastc[idx]     = wlast[idx * 2 + 0];
        g_wlastc[8 + idx] = wlast[idx * 2 + 1] - wlast[idx * 2 + 0];
    }
}

// ---------------- chain inner loop (shared by both sides) ----------------
template<int STEP>
__device__ __forceinline__ void chain_run(const float* __restrict__ sw, int b,
                                          float (&v)[8], int nsteps, int p0idx) {
    float pA = g_pT[p0idx * BB + b];
    float pB = g_pT[(p0idx + STEP) * BB + b];
    for (int s = 0; s < nsteps; s++) {
        const float pc = pA;
        pA = pB;
        pB = g_pT[(p0idx + STEP * (s + 2)) * BB + b];   // prefetch (bounds-safe)
        const ulonglong2* __restrict__ w2 = (const ulonglong2*)(sw + s * 128);
        u64 a0 = 0, a1 = 0, a2 = 0, a3 = 0;
        u64 c0 = 0, c1 = 0, c2 = 0, c3 = 0;
        #pragma unroll
        for (int i = 0; i < 8; i++) {
            u64 vd = pk2(v[i], v[i]);
            ulonglong2 qa = w2[i * 2];
            ulonglong2 qb = w2[i * 2 + 1];
            ulonglong2 qc = w2[16 + i * 2];
            ulonglong2 qd = w2[16 + i * 2 + 1];
            a0 = fma2(vd, qa.x, a0);
            a1 = fma2(vd, qa.y, a1);
            a2 = fma2(vd, qb.x, a2);
            a3 = fma2(vd, qb.y, a3);
            c0 = fma2(vd, qc.x, c0);
            c1 = fma2(vd, qc.y, c1);
            c2 = fma2(vd, qd.x, c2);
            c3 = fma2(vd, qd.y, c3);
        }
        u64 p2 = pk2(pc, pc);
        a0 = fma2(p2, c0, a0);
        a1 = fma2(p2, c1, a1);
        a2 = fma2(p2, c2, a2);
        a3 = fma2(p2, c3, a3);
        upk2(v[0], v[1], a0);
        upk2(v[2], v[3], a1);
        upk2(v[4], v[5], a2);
        upk2(v[6], v[7], a3);
    }
}

// ---------------- kernel 3: both chains ----------------
__global__ __launch_bounds__(224, 1) void chain_kernel() {
    extern __shared__ float sw[];
    const int blk = blockIdx.x;
    const bool isLeft = (blk < 74);
    {
        const float4* g4 = (const float4*)(isLeft ? g_WL : g_WR);
        float4* s4 = (float4*)sw;
        const int n4 = (isLeft ? LLEFT : LRIGHT) * 32;
        for (int i = threadIdx.x; i < n4; i += 224) s4[i] = g4[i];
    }
    __syncthreads();

    const int b = (isLeft ? blk : blk - 74) * 224 + threadIdx.x;
    if (b >= BB) return;

    float v[8];
    if (isLeft) {
        float p0 = g_pT[b];
        #pragma unroll
        for (int d = 0; d < 8; d++) v[d] = fmaf(p0, g_w0c[8 + d], g_w0c[d]);
        chain_run<1>(sw, b, v, LLEFT, 1);
        float4* dst = (float4*)(g_vleft + b * 8);
        dst[0] = make_float4(v[0], v[1], v[2], v[3]);
        dst[1] = make_float4(v[4], v[5], v[6], v[7]);
    } else {
        float pl = g_pT[(NSITES - 1) * BB + b];
        #pragma unroll
        for (int d = 0; d < 8; d++) v[d] = fmaf(pl, g_wlastc[8 + d], g_wlastc[d]);
        chain_run<-1>(sw, b, v, LRIGHT, NSITES - 2);   // steps: sites 782 down to 393
        float4* dst = (float4*)(g_u + b * 8);
        dst[0] = make_float4(v[0], v[1], v[2], v[3]);
        dst[1] = make_float4(v[4], v[5], v[6], v[7]);
    }
}

// ---------------- kernel 4: label combine, 2 threads per batch row ----------------
__global__ __launch_bounds__(256) void label_kernel(float* __restrict__ out) {
    __shared__ float sA[DD * DD * OO];
    __shared__ float sC[DD * DD * OO];
    for (int i = threadIdx.x; i < DD * DD * OO; i += 256) {
        sA[i] = g_Alab[i];
        sC[i] = g_Clab[i];
    }
    __syncthreads();

    const int tid = blockIdx.x * 256 + threadIdx.x;   // 0 .. 32767
    const int b = tid >> 1;
    const int h = tid & 1;                            // d-half

    const float p = g_pT[LABEL * BB + b];
    const u64 p2 = pk2(p, p);

    float vl[4];
    {
        const float4 t = ((const float4*)(g_vleft + b * 8))[h];
        vl[0] = t.x; vl[1] = t.y; vl[2] = t.z; vl[3] = t.w;
    }
    float uu[8];
    {
        const float4* s1 = (const float4*)(g_u + b * 8);
        float4 r0 = s1[0], r1 = s1[1];
        uu[0] = r0.x; uu[1] = r0.y; uu[2] = r0.z; uu[3] = r0.w;
        uu[4] = r1.x; uu[5] = r1.y; uu[6] = r1.z; uu[7] = r1.w;
    }

    u64 acc[5] = {0, 0, 0, 0, 0};
    #pragma unroll
    for (int d4 = 0; d4 < 4; d4++) {
        const int d = h * 4 + d4;
        #pragma unroll
        for (int e = 0; e < 8; e++) {
            const float g = vl[d4] * uu[e];
            const u64 g2 = pk2(g, g);
            const u64 gp2 = mul2(g2, p2);
            const u64* wa = (const u64*)(sA + (d * 8 + e) * OO);
            const u64* wc = (const u64*)(sC + (d * 8 + e) * OO);
            #pragma unroll
            for (int k = 0; k < 5; k++) {
                acc[k] = fma2(g2, wa[k], acc[k]);
                acc[k] = fma2(gp2, wc[k], acc[k]);
            }
        }
    }
    // reduce the two d-halves (lanes differing in bit 0)
    #pragma unroll
    for (int k = 0; k < 5; k++) {
        u64 other = __shfl_xor_sync(0xFFFFFFFFu, acc[k], 1);
        acc[k] = add2(acc[k], other);
    }
    if (h == 0) {
        float2* o2 = (float2*)(out + b * OO);
        #pragma unroll
        for (int k = 0; k < 5; k++) {
            float lo, hi;
            upk2(lo, hi, acc[k]);
            o2[k] = make_float2(lo, hi);
        }
    }
}

// ---------------- launcher ----------------
extern "C" void kernel_launch(void* const* d_in, const int* in_sizes, int n_in,
                              void* d_out, int out_size) {
    const float* x      = (const float*)d_in[0];
    const float* w0     = (const float*)d_in[1];
    const float* Wleft  = (const float*)d_in[2];
    const float* wlabel = (const float*)d_in[3];
    const float* Wright = (const float*)d_in[4];
    const float* wlast  = (const float*)d_in[5];
    float* out = (float*)d_out;

    const int chainSmem = LLEFT * 128 * (int)sizeof(float);   // 200192 B
    cudaFuncSetAttribute(chain_kernel, cudaFuncAttributeMaxDynamicSharedMemorySize, chainSmem);

    transpose_kernel<<<dim3((NSITES + 31) / 32, BB / 32), dim3(32, 8)>>>(x);
    const int prepN = LLEFT * 64 + LRIGHT * 64 + DD * DD * OO + 16;
    prep_weights<<<(prepN + 255) / 256, 256>>>(Wleft, wlabel, Wright, w0, wlast);
    chain_kernel<<<148, 224, chainSmem>>>();
    label_kernel<<<(2 * BB) / 256, 256>>>(out);
}

// round 3
// speedup vs baseline: 2.1261x; 1.4204x over previous
#include <cuda_runtime.h>
#include <cuda_bf16.h>

#define BB      16384
#define NSITES  784
#define DD      8
#define OO      10
#define LABEL   392
#define LLEFT   391   // sites 1..391
#define LRIGHT  390   // sites 393..782 (stored reversed+transposed)

typedef unsigned long long u64;

// ---------------- packed f32x2 helpers ----------------
__device__ __forceinline__ u64 pk2(float a, float b) {
    u64 r; asm("mov.b64 %0, {%1, %2};" : "=l"(r) : "f"(a), "f"(b)); return r;
}
__device__ __forceinline__ void upk2(float& a, float& b, u64 r) {
    asm("mov.b64 {%0, %1}, %2;" : "=f"(a), "=f"(b) : "l"(r));
}
__device__ __forceinline__ u64 fma2(u64 a, u64 b, u64 c) {
    u64 d; asm("fma.rn.f32x2 %0, %1, %2, %3;" : "=l"(d) : "l"(a), "l"(b), "l"(c)); return d;
}
__device__ __forceinline__ u64 mul2(u64 a, u64 b) {
    u64 d; asm("mul.rn.f32x2 %0, %1, %2;" : "=l"(d) : "l"(a), "l"(b)); return d;
}

// ---------------- scratch ----------------
__device__ __align__(16) float g_WL[LLEFT * 128];     // per step: A (64) | C (64)
__device__ __align__(16) float g_WR[LRIGHT * 128];    // transposed + reversed
__device__ __align__(8)  float g_Alab[DD * DD * OO];
__device__ __align__(8)  float g_Clab[DD * DD * OO];
__device__ float g_w0c[16];
__device__ float g_wlastc[16];
__device__ __align__(16) float g_vleft[BB * 8];
__device__ __align__(16) float g_u[BB * 8];
__device__ unsigned g_flag[64];

// ---------------- weight prep ----------------
__global__ void prep_weights(const float* __restrict__ wl,
                             const float* __restrict__ wlab,
                             const float* __restrict__ wr,
                             const float* __restrict__ w0,
                             const float* __restrict__ wlast) {
    int idx = blockIdx.x * blockDim.x + threadIdx.x;
    if (idx < LLEFT * 64) {
        int s = idx >> 6; int r = idx & 63; int d = r >> 3; int e = r & 7;
        float a = wl[((s * 8 + d) * 2 + 0) * 8 + e];
        float b = wl[((s * 8 + d) * 2 + 1) * 8 + e];
        g_WL[s * 128 + d * 8 + e] = a;
        g_WL[s * 128 + 64 + d * 8 + e] = b - a;
        return;
    }
    idx -= LLEFT * 64;
    if (idx < LRIGHT * 64) {           // step t uses site (782 - t), transposed
        int t = idx >> 6; int r = idx & 63; int i = r >> 3; int j = r & 7;
        int site_local = (LRIGHT - 1) - t;
        float a = wr[((site_local * 8 + j) * 2 + 0) * 8 + i];
        float b = wr[((site_local * 8 + j) * 2 + 1) * 8 + i];
        g_WR[t * 128 + i * 8 + j] = a;
        g_WR[t * 128 + 64 + i * 8 + j] = b - a;
        return;
    }
    idx -= LRIGHT * 64;
    if (idx < DD * DD * OO) {
        int o = idx % OO; int de = idx / OO; int e = de & 7; int d = de >> 3;
        float a = wlab[((d * 2 + 0) * 8 + e) * OO + o];
        float b = wlab[((d * 2 + 1) * 8 + e) * OO + o];
        g_Alab[(d * 8 + e) * OO + o] = a;
        g_Clab[(d * 8 + e) * OO + o] = b - a;
        return;
    }
    idx -= DD * DD * OO;
    if (idx < 8) { g_w0c[idx] = w0[idx]; g_w0c[8 + idx] = w0[8 + idx] - w0[idx]; return; }
    idx -= 8;
    if (idx < 8) {
        g_wlastc[idx]     = wlast[idx * 2 + 0];
        g_wlastc[8 + idx] = wlast[idx * 2 + 1] - wlast[idx * 2 + 0];
        return;
    }
    idx -= 8;
    if (idx < 64) g_flag[idx] = 0;
}

// ---------------- one site step for 2 rows ----------------
__device__ __forceinline__ void site_step(const float* __restrict__ wsite,
                                          float (&v0)[8], float (&v1)[8],
                                          float pc0, float pc1) {
    const ulonglong2* __restrict__ w2 = (const ulonglong2*)wsite;
    u64 A0=0,A1=0,A2=0,A3=0, C0=0,C1=0,C2=0,C3=0;
    u64 B0=0,B1=0,B2=0,B3=0, D0=0,D1=0,D2=0,D3=0;
    #pragma unroll
    for (int i = 0; i < 8; i++) {
        u64 vd0 = pk2(v0[i], v0[i]);
        u64 vd1 = pk2(v1[i], v1[i]);
        ulonglong2 qa = w2[2*i],    qb = w2[2*i+1];
        ulonglong2 qc = w2[16+2*i], qd = w2[16+2*i+1];
        A0 = fma2(vd0, qa.x, A0); A1 = fma2(vd0, qa.y, A1);
        A2 = fma2(vd0, qb.x, A2); A3 = fma2(vd0, qb.y, A3);
        C0 = fma2(vd0, qc.x, C0); C1 = fma2(vd0, qc.y, C1);
        C2 = fma2(vd0, qd.x, C2); C3 = fma2(vd0, qd.y, C3);
        B0 = fma2(vd1, qa.x, B0); B1 = fma2(vd1, qa.y, B1);
        B2 = fma2(vd1, qb.x, B2); B3 = fma2(vd1, qb.y, B3);
        D0 = fma2(vd1, qc.x, D0); D1 = fma2(vd1, qc.y, D1);
        D2 = fma2(vd1, qd.x, D2); D3 = fma2(vd1, qd.y, D3);
    }
    u64 p20 = pk2(pc0, pc0), p21 = pk2(pc1, pc1);
    A0 = fma2(p20, C0, A0); A1 = fma2(p20, C1, A1);
    A2 = fma2(p20, C2, A2); A3 = fma2(p20, C3, A3);
    B0 = fma2(p21, D0, B0); B1 = fma2(p21, D1, B1);
    B2 = fma2(p21, D2, B2); B3 = fma2(p21, D3, B3);
    upk2(v0[0], v0[1], A0); upk2(v0[2], v0[3], A1);
    upk2(v0[4], v0[5], A2); upk2(v0[6], v0[7], A3);
    upk2(v1[0], v1[1], B0); upk2(v1[2], v1[3], B1);
    upk2(v1[4], v1[5], B2); upk2(v1[6], v1[7], B3);
}

// ---------------- label combine for one row ----------------
__device__ __forceinline__ void label_row(const u64* __restrict__ sA,
                                          const u64* __restrict__ sC,
                                          const float (&vl)[8], const float (&uu)[8],
                                          float p, float* __restrict__ out, int row) {
    const u64 p2 = pk2(p, p);
    u64 acc[5] = {0, 0, 0, 0, 0};
    #pragma unroll
    for (int d = 0; d < 8; d++) {
        #pragma unroll
        for (int e = 0; e < 8; e++) {
            const float g = vl[d] * uu[e];
            const u64 g2 = pk2(g, g);
            const u64 gp2 = mul2(g2, p2);
            const int base = (d * 8 + e) * 5;
            #pragma unroll
            for (int k = 0; k < 5; k++) {
                acc[k] = fma2(g2, sA[base + k], acc[k]);
                acc[k] = fma2(gp2, sC[base + k], acc[k]);
            }
        }
    }
    float2* o2 = (float2*)(out + row * OO);
    #pragma unroll
    for (int k = 0; k < 5; k++) {
        float lo, hi; upk2(lo, hi, acc[k]);
        o2[k] = make_float2(lo, hi);
    }
}

// ---------------- fused chain + label kernel ----------------
__global__ __launch_bounds__(128, 1) void chain_kernel(const float* __restrict__ x,
                                                       float* __restrict__ out) {
    extern __shared__ float sw[];
    __shared__ unsigned s_old;
    const int blk = blockIdx.x;            // 0..127
    const bool isLeft = blk < 64;
    const int pair = isLeft ? blk : blk - 64;

    {   // stage this side's weights
        const float4* g4 = (const float4*)(isLeft ? g_WL : g_WR);
        float4* s4 = (float4*)sw;
        const int n4 = (isLeft ? LLEFT : LRIGHT) * 32;
        for (int i = threadIdx.x; i < n4; i += 128) s4[i] = g4[i];
    }
    __syncthreads();

    const int r0 = pair * 256 + threadIdx.x;
    const int r1 = r0 + 128;
    const float* px0 = x + (size_t)r0 * NSITES;
    const float* px1 = x + (size_t)r1 * NSITES;

    float v0[8], v1[8];
    if (isLeft) {
        float4 f0 = *(const float4*)(px0);
        float4 f1 = *(const float4*)(px1);
        #pragma unroll
        for (int d = 0; d < 8; d++) {
            v0[d] = fmaf(f0.x, g_w0c[8 + d], g_w0c[d]);
            v1[d] = fmaf(f1.x, g_w0c[8 + d], g_w0c[d]);
        }
        float4 n0 = *(const float4*)(px0 + 4);
        float4 n1 = *(const float4*)(px1 + 4);
        site_step(sw + 0 * 128, v0, v1, f0.y, f1.y);   // site 1
        site_step(sw + 1 * 128, v0, v1, f0.z, f1.z);   // site 2
        site_step(sw + 2 * 128, v0, v1, f0.w, f1.w);   // site 3
        const float* wp = sw + 3 * 128;
        #pragma unroll 1
        for (int g = 1; g <= 97; g++) {                // sites 4g..4g+3
            f0 = n0; f1 = n1;
            n0 = *(const float4*)(px0 + 4 * g + 4);    // g=97 -> 392, valid
            n1 = *(const float4*)(px1 + 4 * g + 4);
            site_step(wp, v0, v1, f0.x, f1.x); wp += 128;
            site_step(wp, v0, v1, f0.y, f1.y); wp += 128;
            site_step(wp, v0, v1, f0.z, f1.z); wp += 128;
            site_step(wp, v0, v1, f0.w, f1.w); wp += 128;
        }
        float4* d0 = (float4*)(g_vleft + r0 * 8);
        d0[0] = make_float4(v0[0], v0[1], v0[2], v0[3]);
        d0[1] = make_float4(v0[4], v0[5], v0[6], v0[7]);
        float4* d1 = (float4*)(g_vleft + r1 * 8);
        d1[0] = make_float4(v1[0], v1[1], v1[2], v1[3]);
        d1[1] = make_float4(v1[4], v1[5], v1[6], v1[7]);
    } else {
        float4 f0 = *(const float4*)(px0 + 780);       // sites 780..783
        float4 f1 = *(const float4*)(px1 + 780);
        #pragma unroll
        for (int d = 0; d < 8; d++) {
            v0[d] = fmaf(f0.w, g_wlastc[8 + d], g_wlastc[d]);
            v1[d] = fmaf(f1.w, g_wlastc[8 + d], g_wlastc[d]);
        }
        float4 n0 = *(const float4*)(px0 + 776);
        float4 n1 = *(const float4*)(px1 + 776);
        site_step(sw + 0 * 128, v0, v1, f0.z, f1.z);   // site 782
        site_step(sw + 1 * 128, v0, v1, f0.y, f1.y);   // site 781
        site_step(sw + 2 * 128, v0, v1, f0.x, f1.x);   // site 780
        const float* wp = sw + 3 * 128;
        #pragma unroll 1
        for (int m = 0; m < 96; m++) {                 // sites 779-4m .. 776-4m
            f0 = n0; f1 = n1;
            n0 = *(const float4*)(px0 + 772 - 4 * m);  // m=95 -> 392; m never OOB
            n1 = *(const float4*)(px1 + 772 - 4 * m);
            site_step(wp, v0, v1, f0.w, f1.w); wp += 128;
            site_step(wp, v0, v1, f0.z, f1.z); wp += 128;
            site_step(wp, v0, v1, f0.y, f1.y); wp += 128;
            site_step(wp, v0, v1, f0.x, f1.x); wp += 128;
        }
        f0 = n0; f1 = n1;                              // base 392: sites 395,394,393
        site_step(wp, v0, v1, f0.w, f1.w); wp += 128;
        site_step(wp, v0, v1, f0.z, f1.z); wp += 128;
        site_step(wp, v0, v1, f0.y, f1.y);
        float4* d0 = (float4*)(g_u + r0 * 8);
        d0[0] = make_float4(v0[0], v0[1], v0[2], v0[3]);
        d0[1] = make_float4(v0[4], v0[5], v0[6], v0[7]);
        float4* d1 = (float4*)(g_u + r1 * 8);
        d1[0] = make_float4(v1[0], v1[1], v1[2], v1[3]);
        d1[1] = make_float4(v1[4], v1[5], v1[6], v1[7]);
    }

    // ---- handoff: second CTA of the pair computes the label combine ----
    __threadfence();                                   // release our stores
    __syncthreads();
    if (threadIdx.x == 0) s_old = atomicAdd(&g_flag[pair], 1u);
    __syncthreads();
    if (s_old == 0) return;                            // first arriver exits
    __threadfence();                                   // acquire other side's stores

    // stage label weights into (now free) SMEM
    for (int i = threadIdx.x; i < 640; i += 128) {
        ((u64*)sw)[i]       = ((const u64*)g_Alab)[i];
        ((u64*)sw)[640 + i] = ((const u64*)g_Clab)[i];
    }
    __syncthreads();
    const u64* sA = (const u64*)sw;
    const u64* sC = sA + 640;

    const float* other = isLeft ? g_u : g_vleft;
    float o0[8], o1[8];
    {
        const float4* s0 = (const float4*)(other + r0 * 8);
        float4 a = s0[0], b = s0[1];
        o0[0]=a.x; o0[1]=a.y; o0[2]=a.z; o0[3]=a.w; o0[4]=b.x; o0[5]=b.y; o0[6]=b.z; o0[7]=b.w;
        const float4* s1 = (const float4*)(other + r1 * 8);
        float4 c = s1[0], d = s1[1];
        o1[0]=c.x; o1[1]=c.y; o1[2]=c.z; o1[3]=c.w; o1[4]=d.x; o1[5]=d.y; o1[6]=d.z; o1[7]=d.w;
    }
    const float pl0 = px0[LABEL];
    const float pl1 = px1[LABEL];
    if (isLeft) {
        label_row(sA, sC, v0, o0, pl0, out, r0);
        label_row(sA, sC, v1, o1, pl1, out, r1);
    } else {
        label_row(sA, sC, o0, v0, pl0, out, r0);
        label_row(sA, sC, o1, v1, pl1, out, r1);
    }
}

// ---------------- launcher ----------------
extern "C" void kernel_launch(void* const* d_in, const int* in_sizes, int n_in,
                              void* d_out, int out_size) {
    const float* x      = (const float*)d_in[0];
    const float* w0     = (const float*)d_in[1];
    const float* Wleft  = (const float*)d_in[2];
    const float* wlabel = (const float*)d_in[3];
    const float* Wright = (const float*)d_in[4];
    const float* wlast  = (const float*)d_in[5];
    float* out = (float*)d_out;

    const int chainSmem = LLEFT * 128 * (int)sizeof(float);   // 200192 B
    cudaFuncSetAttribute(chain_kernel, cudaFuncAttributeMaxDynamicSharedMemorySize, chainSmem);

    const int prepN = LLEFT * 64 + LRIGHT * 64 + DD * DD * OO + 8 + 8 + 64;
    prep_weights<<<(prepN + 255) / 256, 256>>>(Wleft, wlabel, Wright, w0, wlast);
    chain_kernel<<<128, 128, chainSmem>>>(x, out);
}